// round 3
// baseline (speedup 1.0000x reference)
#include <cuda_runtime.h>
#include <cuda_bf16.h>
#include <math.h>

// Problem constants
#define B 2
#define S 2048
#define EMB 2048
#define NH 32
#define NKV 8
#define HD 64
#define KV_DIM (NKV * HD)   // 512
#define M_ROWS (B * S)      // 4096

// Scratch (device globals; no allocation allowed)
__device__ float g_Q[M_ROWS * EMB];      // 32 MB
__device__ float g_K[M_ROWS * KV_DIM];   //  8 MB
__device__ float g_V[M_ROWS * KV_DIM];   //  8 MB
__device__ float g_C[M_ROWS * EMB];      // 32 MB  (attention context)

// ---------------------------------------------------------------------------
// Tiled SGEMM: C[M,N] = A[M,K] * Bm[K,N], row-major, all dims multiple of 64.
// 64x64 block tile, 256 threads, 4x4 per-thread tile, K-chunks of 16.
// ---------------------------------------------------------------------------
#define TS 64
#define KT 16

__global__ void __launch_bounds__(256)
sgemm_kernel(const float* __restrict__ A, const float* __restrict__ Bm,
             float* __restrict__ C, int M, int N, int K)
{
    __shared__ float As[KT][TS];   // transposed: As[k][m]
    __shared__ float Bs[KT][TS];   // Bs[k][n]

    const int tid = threadIdx.x;
    const int tx = tid & 15;
    const int ty = tid >> 4;
    const int bm = blockIdx.y * TS;
    const int bn = blockIdx.x * TS;

    float acc[4][4] = {};

    for (int k0 = 0; k0 < K; k0 += KT) {
        // Load A tile 64x16 (each thread one float4), store transposed
        {
            int r  = tid >> 2;          // 0..63
            int c4 = (tid & 3) * 4;     // 0,4,8,12
            float4 v = *(const float4*)&A[(size_t)(bm + r) * K + k0 + c4];
            As[c4 + 0][r] = v.x;
            As[c4 + 1][r] = v.y;
            As[c4 + 2][r] = v.z;
            As[c4 + 3][r] = v.w;
        }
        // Load B tile 16x64 (each thread one float4)
        {
            int r  = tid >> 4;          // 0..15
            int c4 = (tid & 15) * 4;    // 0..60
            float4 v = *(const float4*)&Bm[(size_t)(k0 + r) * N + bn + c4];
            *(float4*)&Bs[r][c4] = v;
        }
        __syncthreads();

        #pragma unroll
        for (int kk = 0; kk < KT; kk++) {
            float4 a4 = *(const float4*)&As[kk][ty * 4];
            float4 b4 = *(const float4*)&Bs[kk][tx * 4];
            float a[4] = {a4.x, a4.y, a4.z, a4.w};
            float b[4] = {b4.x, b4.y, b4.z, b4.w};
            #pragma unroll
            for (int i = 0; i < 4; i++)
                #pragma unroll
                for (int j = 0; j < 4; j++)
                    acc[i][j] = fmaf(a[i], b[j], acc[i][j]);
        }
        __syncthreads();
    }

    #pragma unroll
    for (int i = 0; i < 4; i++) {
        float4 v = make_float4(acc[i][0], acc[i][1], acc[i][2], acc[i][3]);
        *(float4*)&C[(size_t)(bm + ty * 4 + i) * N + bn + tx * 4] = v;
    }
}

// ---------------------------------------------------------------------------
// Flash-attention (fp32, online softmax).
// Grid: (S/64 q-tiles, NH heads, B). Block: 256 threads (16x16).
// Q tile 64 rows, K/V tiles 32 rows. Each thread: 4 q-rows x 2 k-cols scores,
// 4x4 output tile. All smem layouts chosen to be conflict-(near-)free.
// ---------------------------------------------------------------------------
#define QT 64
#define KTile 32

__global__ void __launch_bounds__(256)
attn_kernel(const float* __restrict__ Q, const float* __restrict__ K,
            const float* __restrict__ V, float* __restrict__ ctx)
{
    __shared__ float Qs[HD][QT];         // [d][q]  16 KB
    __shared__ float Ks[HD][KTile];      // [d][k]   8 KB
    __shared__ float Vs[KTile][HD];      // [k][n]   8 KB
    __shared__ float Ps[KTile][QT + 4];  // [k][q] padded  8.5 KB

    const int tid = threadIdx.x;
    const int tx  = tid & 15;
    const int ty  = tid >> 4;
    const int qt  = blockIdx.x;
    const int h   = blockIdx.y;
    const int b   = blockIdx.z;
    const int hkv = h >> 2;          // NUM_Q_PER_KV = 4
    const int q0  = qt * QT;
    const float scale = 0.125f;      // 1/sqrt(HD)

    // Load Q tile, transposed + pre-scaled. 64x64 floats = 1024 float4.
    for (int t = tid; t < QT * (HD / 4); t += 256) {
        int r  = t >> 4;             // q row 0..63
        int c4 = (t & 15) * 4;       // d
        float4 v = *(const float4*)&Q[((size_t)(b * S + q0 + r)) * EMB + h * HD + c4];
        Qs[c4 + 0][r] = v.x * scale;
        Qs[c4 + 1][r] = v.y * scale;
        Qs[c4 + 2][r] = v.z * scale;
        Qs[c4 + 3][r] = v.w * scale;
    }

    float m[4], l[4], acc[4][4];
    #pragma unroll
    for (int i = 0; i < 4; i++) {
        m[i] = -1e30f;
        l[i] = 0.f;
        #pragma unroll
        for (int j = 0; j < 4; j++) acc[i][j] = 0.f;
    }
    __syncthreads();

    for (int k0 = 0; k0 < S; k0 += KTile) {
        // Load K tile transposed, V tile direct. Each 32x64 = 512 float4.
        for (int t = tid; t < KTile * (HD / 4); t += 256) {
            int kk = t >> 4;
            int c4 = (t & 15) * 4;
            size_t grow = ((size_t)(b * S + k0 + kk)) * KV_DIM + hkv * HD + c4;
            float4 kv = *(const float4*)&K[grow];
            Ks[c4 + 0][kk] = kv.x;
            Ks[c4 + 1][kk] = kv.y;
            Ks[c4 + 2][kk] = kv.z;
            Ks[c4 + 3][kk] = kv.w;
            float4 vv = *(const float4*)&V[grow];
            *(float4*)&Vs[kk][c4] = vv;
        }
        __syncthreads();

        // Scores: s[i][j] for q = ty*4+i, k = tx*2+j
        float s[4][2] = {};
        #pragma unroll 8
        for (int d = 0; d < HD; d++) {
            float4 qv = *(const float4*)&Qs[d][ty * 4];
            float2 kv = *(const float2*)&Ks[d][tx * 2];
            float qa[4] = {qv.x, qv.y, qv.z, qv.w};
            #pragma unroll
            for (int i = 0; i < 4; i++) {
                s[i][0] = fmaf(qa[i], kv.x, s[i][0]);
                s[i][1] = fmaf(qa[i], kv.y, s[i][1]);
            }
        }

        // Online softmax per row (reduce over 16 tx-lanes, xor<16 keeps warp half)
        #pragma unroll
        for (int i = 0; i < 4; i++) {
            float tmax = fmaxf(s[i][0], s[i][1]);
            #pragma unroll
            for (int msk = 1; msk < 16; msk <<= 1)
                tmax = fmaxf(tmax, __shfl_xor_sync(0xffffffffu, tmax, msk));
            float mnew = fmaxf(m[i], tmax);
            float p0 = __expf(s[i][0] - mnew);
            float p1 = __expf(s[i][1] - mnew);
            Ps[tx * 2 + 0][ty * 4 + i] = p0;
            Ps[tx * 2 + 1][ty * 4 + i] = p1;
            float ls = p0 + p1;
            #pragma unroll
            for (int msk = 1; msk < 16; msk <<= 1)
                ls += __shfl_xor_sync(0xffffffffu, ls, msk);
            float sc = __expf(m[i] - mnew);
            l[i] = l[i] * sc + ls;
            m[i] = mnew;
            #pragma unroll
            for (int j = 0; j < 4; j++) acc[i][j] *= sc;
        }
        __syncthreads();

        // O += P * V
        #pragma unroll 8
        for (int kk = 0; kk < KTile; kk++) {
            float4 p4 = *(const float4*)&Ps[kk][ty * 4];
            float4 v4 = *(const float4*)&Vs[kk][tx * 4];
            float p[4] = {p4.x, p4.y, p4.z, p4.w};
            float v[4] = {v4.x, v4.y, v4.z, v4.w};
            #pragma unroll
            for (int i = 0; i < 4; i++)
                #pragma unroll
                for (int j = 0; j < 4; j++)
                    acc[i][j] = fmaf(p[i], v[j], acc[i][j]);
        }
        __syncthreads();
    }

    // Normalize and write ctx[b, q, h*HD + d]
    #pragma unroll
    for (int i = 0; i < 4; i++) {
        float inv = 1.0f / l[i];
        float4 v = make_float4(acc[i][0] * inv, acc[i][1] * inv,
                               acc[i][2] * inv, acc[i][3] * inv);
        *(float4*)&ctx[((size_t)(b * S + q0 + ty * 4 + i)) * EMB + h * HD + tx * 4] = v;
    }
}

// ---------------------------------------------------------------------------
extern "C" void kernel_launch(void* const* d_in, const int* in_sizes, int n_in,
                              void* d_out, int out_size)
{
    const float* query = (const float*)d_in[0];
    const float* key   = (const float*)d_in[1];
    const float* value = (const float*)d_in[2];
    const float* Wq    = (const float*)d_in[3];
    const float* Wk    = (const float*)d_in[4];
    const float* Wv    = (const float*)d_in[5];
    const float* Wo    = (const float*)d_in[6];
    float* out = (float*)d_out;

    float *gQ, *gK, *gV, *gC;
    cudaGetSymbolAddress((void**)&gQ, g_Q);
    cudaGetSymbolAddress((void**)&gK, g_K);
    cudaGetSymbolAddress((void**)&gV, g_V);
    cudaGetSymbolAddress((void**)&gC, g_C);

    // Projections
    sgemm_kernel<<<dim3(EMB / TS,    M_ROWS / TS), 256>>>(query, Wq, gQ, M_ROWS, EMB,    EMB);
    sgemm_kernel<<<dim3(KV_DIM / TS, M_ROWS / TS), 256>>>(key,   Wk, gK, M_ROWS, KV_DIM, EMB);
    sgemm_kernel<<<dim3(KV_DIM / TS, M_ROWS / TS), 256>>>(value, Wv, gV, M_ROWS, KV_DIM, EMB);

    // Attention
    attn_kernel<<<dim3(S / QT, NH, B), 256>>>(gQ, gK, gV, gC);

    // Output projection
    sgemm_kernel<<<dim3(EMB / TS, M_ROWS / TS), 256>>>(gC, Wo, out, M_ROWS, EMB, EMB);
}

// round 4
// speedup vs baseline: 1.0012x; 1.0012x over previous
#include <cuda_runtime.h>
#include <cuda_bf16.h>
#include <math.h>

// Problem constants
#define B 2
#define S 2048
#define EMB 2048
#define NH 32
#define NKV 8
#define HD 64
#define KV_DIM (NKV * HD)   // 512
#define M_ROWS (B * S)      // 4096

// Scratch (device globals; no allocation allowed)
__device__ float g_Q[M_ROWS * EMB];      // 32 MB
__device__ float g_K[M_ROWS * KV_DIM];   //  8 MB
__device__ float g_V[M_ROWS * KV_DIM];   //  8 MB
__device__ float g_C[M_ROWS * EMB];      // 32 MB  (attention context)

// ---------------------------------------------------------------------------
// Tiled SGEMM: C[M,N] = A[M,K] * Bm[K,N], row-major, all dims multiple of 64.
// 64x64 block tile, 256 threads, 4x4 per-thread tile, K-chunks of 16.
// ---------------------------------------------------------------------------
#define TS 64
#define KT 16

__global__ void __launch_bounds__(256)
sgemm_kernel(const float* __restrict__ A, const float* __restrict__ Bm,
             float* __restrict__ C, int M, int N, int K)
{
    __shared__ float As[KT][TS];   // transposed: As[k][m]
    __shared__ float Bs[KT][TS];   // Bs[k][n]

    const int tid = threadIdx.x;
    const int tx = tid & 15;
    const int ty = tid >> 4;
    const int bm = blockIdx.y * TS;
    const int bn = blockIdx.x * TS;

    float acc[4][4] = {};

    for (int k0 = 0; k0 < K; k0 += KT) {
        // Load A tile 64x16 (each thread one float4), store transposed
        {
            int r  = tid >> 2;          // 0..63
            int c4 = (tid & 3) * 4;     // 0,4,8,12
            float4 v = *(const float4*)&A[(size_t)(bm + r) * K + k0 + c4];
            As[c4 + 0][r] = v.x;
            As[c4 + 1][r] = v.y;
            As[c4 + 2][r] = v.z;
            As[c4 + 3][r] = v.w;
        }
        // Load B tile 16x64 (each thread one float4)
        {
            int r  = tid >> 4;          // 0..15
            int c4 = (tid & 15) * 4;    // 0..60
            float4 v = *(const float4*)&Bm[(size_t)(k0 + r) * N + bn + c4];
            *(float4*)&Bs[r][c4] = v;
        }
        __syncthreads();

        #pragma unroll
        for (int kk = 0; kk < KT; kk++) {
            float4 a4 = *(const float4*)&As[kk][ty * 4];
            float4 b4 = *(const float4*)&Bs[kk][tx * 4];
            float a[4] = {a4.x, a4.y, a4.z, a4.w};
            float b[4] = {b4.x, b4.y, b4.z, b4.w};
            #pragma unroll
            for (int i = 0; i < 4; i++)
                #pragma unroll
                for (int j = 0; j < 4; j++)
                    acc[i][j] = fmaf(a[i], b[j], acc[i][j]);
        }
        __syncthreads();
    }

    #pragma unroll
    for (int i = 0; i < 4; i++) {
        float4 v = make_float4(acc[i][0], acc[i][1], acc[i][2], acc[i][3]);
        *(float4*)&C[(size_t)(bm + ty * 4 + i) * N + bn + tx * 4] = v;
    }
}

// ---------------------------------------------------------------------------
// Flash-attention (fp32, online softmax).
// Grid: (S/64 q-tiles, NH heads, B). Block: 256 threads (16x16).
// Q tile 64 rows, K/V tiles 32 rows. Each thread: 4 q-rows x 2 k-cols scores,
// 4x4 output tile. All smem layouts chosen to be conflict-(near-)free.
// ---------------------------------------------------------------------------
#define QT 64
#define KTile 32

__global__ void __launch_bounds__(256)
attn_kernel(const float* __restrict__ Q, const float* __restrict__ K,
            const float* __restrict__ V, float* __restrict__ ctx)
{
    __shared__ float Qs[HD][QT];         // [d][q]  16 KB
    __shared__ float Ks[HD][KTile];      // [d][k]   8 KB
    __shared__ float Vs[KTile][HD];      // [k][n]   8 KB
    __shared__ float Ps[KTile][QT + 4];  // [k][q] padded  8.5 KB

    const int tid = threadIdx.x;
    const int tx  = tid & 15;
    const int ty  = tid >> 4;
    const int qt  = blockIdx.x;
    const int h   = blockIdx.y;
    const int b   = blockIdx.z;
    const int hkv = h >> 2;          // NUM_Q_PER_KV = 4
    const int q0  = qt * QT;
    const float scale = 0.125f;      // 1/sqrt(HD)

    // Load Q tile, transposed + pre-scaled. 64x64 floats = 1024 float4.
    for (int t = tid; t < QT * (HD / 4); t += 256) {
        int r  = t >> 4;             // q row 0..63
        int c4 = (t & 15) * 4;       // d
        float4 v = *(const float4*)&Q[((size_t)(b * S + q0 + r)) * EMB + h * HD + c4];
        Qs[c4 + 0][r] = v.x * scale;
        Qs[c4 + 1][r] = v.y * scale;
        Qs[c4 + 2][r] = v.z * scale;
        Qs[c4 + 3][r] = v.w * scale;
    }

    float m[4], l[4], acc[4][4];
    #pragma unroll
    for (int i = 0; i < 4; i++) {
        m[i] = -1e30f;
        l[i] = 0.f;
        #pragma unroll
        for (int j = 0; j < 4; j++) acc[i][j] = 0.f;
    }
    __syncthreads();

    for (int k0 = 0; k0 < S; k0 += KTile) {
        // Load K tile transposed, V tile direct. Each 32x64 = 512 float4.
        for (int t = tid; t < KTile * (HD / 4); t += 256) {
            int kk = t >> 4;
            int c4 = (t & 15) * 4;
            size_t grow = ((size_t)(b * S + k0 + kk)) * KV_DIM + hkv * HD + c4;
            float4 kv = *(const float4*)&K[grow];
            Ks[c4 + 0][kk] = kv.x;
            Ks[c4 + 1][kk] = kv.y;
            Ks[c4 + 2][kk] = kv.z;
            Ks[c4 + 3][kk] = kv.w;
            float4 vv = *(const float4*)&V[grow];
            *(float4*)&Vs[kk][c4] = vv;
        }
        __syncthreads();

        // Scores: s[i][j] for q = ty*4+i, k = tx*2+j
        float s[4][2] = {};
        #pragma unroll 8
        for (int d = 0; d < HD; d++) {
            float4 qv = *(const float4*)&Qs[d][ty * 4];
            float2 kv = *(const float2*)&Ks[d][tx * 2];
            float qa[4] = {qv.x, qv.y, qv.z, qv.w};
            #pragma unroll
            for (int i = 0; i < 4; i++) {
                s[i][0] = fmaf(qa[i], kv.x, s[i][0]);
                s[i][1] = fmaf(qa[i], kv.y, s[i][1]);
            }
        }

        // Online softmax per row (reduce over 16 tx-lanes, xor<16 keeps warp half)
        #pragma unroll
        for (int i = 0; i < 4; i++) {
            float tmax = fmaxf(s[i][0], s[i][1]);
            #pragma unroll
            for (int msk = 1; msk < 16; msk <<= 1)
                tmax = fmaxf(tmax, __shfl_xor_sync(0xffffffffu, tmax, msk));
            float mnew = fmaxf(m[i], tmax);
            float p0 = __expf(s[i][0] - mnew);
            float p1 = __expf(s[i][1] - mnew);
            Ps[tx * 2 + 0][ty * 4 + i] = p0;
            Ps[tx * 2 + 1][ty * 4 + i] = p1;
            float ls = p0 + p1;
            #pragma unroll
            for (int msk = 1; msk < 16; msk <<= 1)
                ls += __shfl_xor_sync(0xffffffffu, ls, msk);
            float sc = __expf(m[i] - mnew);
            l[i] = l[i] * sc + ls;
            m[i] = mnew;
            #pragma unroll
            for (int j = 0; j < 4; j++) acc[i][j] *= sc;
        }
        __syncthreads();

        // O += P * V
        #pragma unroll 8
        for (int kk = 0; kk < KTile; kk++) {
            float4 p4 = *(const float4*)&Ps[kk][ty * 4];
            float4 v4 = *(const float4*)&Vs[kk][tx * 4];
            float p[4] = {p4.x, p4.y, p4.z, p4.w};
            float v[4] = {v4.x, v4.y, v4.z, v4.w};
            #pragma unroll
            for (int i = 0; i < 4; i++)
                #pragma unroll
                for (int j = 0; j < 4; j++)
                    acc[i][j] = fmaf(p[i], v[j], acc[i][j]);
        }
        __syncthreads();
    }

    // Normalize and write ctx[b, q, h*HD + d]
    #pragma unroll
    for (int i = 0; i < 4; i++) {
        float inv = 1.0f / l[i];
        float4 v = make_float4(acc[i][0] * inv, acc[i][1] * inv,
                               acc[i][2] * inv, acc[i][3] * inv);
        *(float4*)&ctx[((size_t)(b * S + q0 + ty * 4 + i)) * EMB + h * HD + tx * 4] = v;
    }
}

// ---------------------------------------------------------------------------
extern "C" void kernel_launch(void* const* d_in, const int* in_sizes, int n_in,
                              void* d_out, int out_size)
{
    const float* query = (const float*)d_in[0];
    const float* key   = (const float*)d_in[1];
    const float* value = (const float*)d_in[2];
    const float* Wq    = (const float*)d_in[3];
    const float* Wk    = (const float*)d_in[4];
    const float* Wv    = (const float*)d_in[5];
    const float* Wo    = (const float*)d_in[6];
    float* out = (float*)d_out;

    float *gQ, *gK, *gV, *gC;
    cudaGetSymbolAddress((void**)&gQ, g_Q);
    cudaGetSymbolAddress((void**)&gK, g_K);
    cudaGetSymbolAddress((void**)&gV, g_V);
    cudaGetSymbolAddress((void**)&gC, g_C);

    // Projections
    sgemm_kernel<<<dim3(EMB / TS,    M_ROWS / TS), 256>>>(query, Wq, gQ, M_ROWS, EMB,    EMB);
    sgemm_kernel<<<dim3(KV_DIM / TS, M_ROWS / TS), 256>>>(key,   Wk, gK, M_ROWS, KV_DIM, EMB);
    sgemm_kernel<<<dim3(KV_DIM / TS, M_ROWS / TS), 256>>>(value, Wv, gV, M_ROWS, KV_DIM, EMB);

    // Attention
    attn_kernel<<<dim3(S / QT, NH, B), 256>>>(gQ, gK, gV, gC);

    // Output projection
    sgemm_kernel<<<dim3(EMB / TS, M_ROWS / TS), 256>>>(gC, Wo, out, M_ROWS, EMB, EMB);
}

// round 5
// speedup vs baseline: 2.4226x; 2.4196x over previous
#include <cuda_runtime.h>
#include <cuda_bf16.h>
#include <math.h>

// Problem constants
#define B 2
#define S 2048
#define EMB 2048
#define NH 32
#define NKV 8
#define HD 64
#define KV_DIM (NKV * HD)   // 512
#define M_ROWS (B * S)      // 4096

// Scratch (device globals; no allocation allowed)
__device__ float g_Q[M_ROWS * EMB];      // 32 MB
__device__ float g_K[M_ROWS * KV_DIM];   //  8 MB
__device__ float g_V[M_ROWS * KV_DIM];   //  8 MB
__device__ float g_C[M_ROWS * EMB];      // 32 MB

// ---------------------------------------------------------------------------
// Helpers
// ---------------------------------------------------------------------------
__device__ __forceinline__ unsigned f2tf32(float x) {
    unsigned r; asm("cvt.rna.tf32.f32 %0, %1;" : "=r"(r) : "f"(x)); return r;
}
__device__ __forceinline__ float ex2f_fast(float x) {
    float r; asm("ex2.approx.f32 %0, %1;" : "=f"(r) : "f"(x)); return r;
}
// D += A(16x8,row) * B(8x8,col), tf32 inputs, f32 accum
__device__ __forceinline__ void mma8(float* c, unsigned a0, unsigned a1,
                                     unsigned a2, unsigned a3,
                                     unsigned b0, unsigned b1) {
    asm volatile(
        "mma.sync.aligned.m16n8k8.row.col.f32.tf32.tf32.f32 "
        "{%0,%1,%2,%3}, {%4,%5,%6,%7}, {%8,%9}, {%0,%1,%2,%3};"
        : "+f"(c[0]), "+f"(c[1]), "+f"(c[2]), "+f"(c[3])
        : "r"(a0), "r"(a1), "r"(a2), "r"(a3), "r"(b0), "r"(b1));
}

// ---------------------------------------------------------------------------
// tf32 tensor-core GEMM: C[M,N] = A[M,K] * Bm[K,N], row-major fp32.
// 128x128 block tile, BK=16, 256 threads (8 warps, 4x2 warp grid, 32x64/warp).
// A stored k-permuted (k' = (k%4)*4 + k/4 per 16-group) so each A fragment is
// one LDS.128; B padded to stride 136 so scalar frag reads are conflict-free.
// ---------------------------------------------------------------------------
__global__ void __launch_bounds__(256)
gemm_tf32(const float* __restrict__ A, const float* __restrict__ Bm,
          float* __restrict__ C, int M, int N, int K)
{
    __shared__ __align__(16) unsigned As[2][128][16];
    __shared__ __align__(16) unsigned Bs[2][16][136];

    const int tid  = threadIdx.x;
    const int lane = tid & 31;
    const int warp = tid >> 5;
    const int wm = warp >> 1, wn = warp & 1;
    const int g = lane >> 2, j = lane & 3;
    const int bm = blockIdx.y * 128, bn = blockIdx.x * 128;

    // loader mapping
    const int arow = tid >> 2;          // 0..63 (and +64)
    const int aq   = tid & 3;           // k-group of 4
    const int brow = tid >> 4;          // 0..15
    const int bcol = (tid & 15) * 8;    // 0..120

    const float* Ap = A  + (size_t)(bm + arow) * K + aq * 4;
    const float* Bp = Bm + (size_t)brow * N + bn + bcol;

    float4 aR0 = *(const float4*)Ap;
    float4 aR1 = *(const float4*)(Ap + (size_t)64 * K);
    float4 bR0 = *(const float4*)Bp;
    float4 bR1 = *(const float4*)(Bp + 4);

    float c[2][8][4];
    #pragma unroll
    for (int mt = 0; mt < 2; mt++)
        #pragma unroll
        for (int nt = 0; nt < 8; nt++)
            #pragma unroll
            for (int e = 0; e < 4; e++) c[mt][nt][e] = 0.f;

    const int nc = K / 16;
    for (int ci = 0; ci < nc; ci++) {
        const int buf = ci & 1;
        // stage regs -> smem (A permuted scatter; B vectorized)
        {
            unsigned* ad = &As[buf][arow][aq];
            ad[0]  = f2tf32(aR0.x); ad[4]  = f2tf32(aR0.y);
            ad[8]  = f2tf32(aR0.z); ad[12] = f2tf32(aR0.w);
            unsigned* ad2 = &As[buf][arow + 64][aq];
            ad2[0]  = f2tf32(aR1.x); ad2[4]  = f2tf32(aR1.y);
            ad2[8]  = f2tf32(aR1.z); ad2[12] = f2tf32(aR1.w);
            uint4 w0 = make_uint4(f2tf32(bR0.x), f2tf32(bR0.y), f2tf32(bR0.z), f2tf32(bR0.w));
            uint4 w1 = make_uint4(f2tf32(bR1.x), f2tf32(bR1.y), f2tf32(bR1.z), f2tf32(bR1.w));
            *(uint4*)&Bs[buf][brow][bcol]     = w0;
            *(uint4*)&Bs[buf][brow][bcol + 4] = w1;
        }
        __syncthreads();

        // prefetch next chunk into regs (overlaps with MMA below)
        if (ci + 1 < nc) {
            Ap += 16; Bp += (size_t)16 * N;
            aR0 = *(const float4*)Ap;
            aR1 = *(const float4*)(Ap + (size_t)64 * K);
            bR0 = *(const float4*)Bp;
            bR1 = *(const float4*)(Bp + 4);
        }

        // A fragments: one LDS.128 per (mtile,row-half) covers both k-steps
        uint4 av[2][2];
        #pragma unroll
        for (int mt = 0; mt < 2; mt++) {
            av[mt][0] = *(const uint4*)&As[buf][wm * 32 + mt * 16 + g][j * 4];
            av[mt][1] = *(const uint4*)&As[buf][wm * 32 + mt * 16 + g + 8][j * 4];
        }
        #pragma unroll
        for (int ks = 0; ks < 2; ks++) {
            unsigned bb[8][2];
            #pragma unroll
            for (int nt = 0; nt < 8; nt++) {
                bb[nt][0] = Bs[buf][ks * 8 + j][wn * 64 + nt * 8 + g];
                bb[nt][1] = Bs[buf][ks * 8 + j + 4][wn * 64 + nt * 8 + g];
            }
            #pragma unroll
            for (int mt = 0; mt < 2; mt++) {
                unsigned a0, a1, a2, a3;
                if (ks == 0) { a0 = av[mt][0].x; a1 = av[mt][1].x; a2 = av[mt][0].y; a3 = av[mt][1].y; }
                else         { a0 = av[mt][0].z; a1 = av[mt][1].z; a2 = av[mt][0].w; a3 = av[mt][1].w; }
                #pragma unroll
                for (int nt = 0; nt < 8; nt++)
                    mma8(c[mt][nt], a0, a1, a2, a3, bb[nt][0], bb[nt][1]);
            }
        }
        // single sync per iter: next iter stores to the other buffer; the
        // matched barrier guarantees no warp is >1 buffer behind.
    }

    #pragma unroll
    for (int mt = 0; mt < 2; mt++) {
        int r0 = bm + wm * 32 + mt * 16 + g;
        #pragma unroll
        for (int nt = 0; nt < 8; nt++) {
            int col = bn + wn * 64 + nt * 8 + 2 * j;
            *(float2*)&C[(size_t)r0 * N + col]       = make_float2(c[mt][nt][0], c[mt][nt][1]);
            *(float2*)&C[(size_t)(r0 + 8) * N + col] = make_float2(c[mt][nt][2], c[mt][nt][3]);
        }
    }
}

// ---------------------------------------------------------------------------
// Flash attention with tf32 mma. Block = (64 q-rows, head, batch), 128 thr.
// Each warp: 16 q-rows. Q frags resident in registers. K/V chunks of 64
// tokens in smem (transposed + k-permuted + stride-80 pad: conflict-free
// LDS.128 fragments). P goes through per-warp smem (permuted scatter).
// ---------------------------------------------------------------------------
#define ATTN_SMEM (2 * 64 * 80 * 4 + 4 * 16 * 80 * 4)   // 61440 bytes

__global__ void __launch_bounds__(128)
attn_tf32(const float* __restrict__ Q, const float* __restrict__ Kg,
          const float* __restrict__ Vg, float* __restrict__ ctx)
{
    extern __shared__ __align__(16) unsigned smu[];
    unsigned* Ks = smu;                      // [64 tok][80]  (d permuted)
    unsigned* Vs = smu + 64 * 80;            // [64 d][80]    (tok permuted)
    unsigned* Ps = smu + 2 * 64 * 80 + (threadIdx.x >> 5) * 16 * 80;  // per-warp

    const int tid  = threadIdx.x;
    const int lane = tid & 31;
    const int warp = tid >> 5;
    const int g = lane >> 2, j = lane & 3;
    const int h = blockIdx.y, b = blockIdx.z;
    const int hkv = h >> 2;                  // NUM_Q_PER_KV = 4
    const int q0 = blockIdx.x * 64;

    // Preload Q fragments (pre-scaled by 1/sqrt(D) * log2(e) for ex2 softmax)
    unsigned qa[8][4];
    {
        const float* qp = Q + ((size_t)(b * S + q0 + warp * 16 + g)) * EMB + h * HD;
        const float qs = 0.125f * 1.4426950408889634f;
        #pragma unroll
        for (int ks = 0; ks < 8; ks++) {
            qa[ks][0] = f2tf32(qp[ks * 8 + j] * qs);
            qa[ks][1] = f2tf32(qp[(size_t)8 * EMB + ks * 8 + j] * qs);
            qa[ks][2] = f2tf32(qp[ks * 8 + j + 4] * qs);
            qa[ks][3] = f2tf32(qp[(size_t)8 * EMB + ks * 8 + j + 4] * qs);
        }
    }

    float m0 = -1e30f, m1 = -1e30f, l0 = 0.f, l1 = 0.f;
    float o[8][4];
    #pragma unroll
    for (int nt = 0; nt < 8; nt++)
        #pragma unroll
        for (int e = 0; e < 4; e++) o[nt][e] = 0.f;

    for (int k0 = 0; k0 < S; k0 += 64) {
        // --- load K/V chunk (transpose + permute + tf32 convert) ---
        #pragma unroll
        for (int i = 0; i < 8; i++) {
            int f4  = i * 128 + tid;         // 0..1023 float4 units
            int tok = f4 >> 4;
            int q4  = f4 & 15;
            size_t grow = ((size_t)(b * S + k0 + tok)) * KV_DIM + hkv * HD + q4 * 4;
            float4 kv = *(const float4*)&Kg[grow];
            unsigned* kd = Ks + tok * 80 + (q4 >> 2) * 16 + (q4 & 3);
            kd[0]  = f2tf32(kv.x); kd[4]  = f2tf32(kv.y);
            kd[8]  = f2tf32(kv.z); kd[12] = f2tf32(kv.w);
            float4 vv = *(const float4*)&Vg[grow];
            int tkl  = tok & 15;
            int tokp = (tok & 48) + (tkl & 3) * 4 + (tkl >> 2);
            unsigned* vd = Vs + (q4 * 4) * 80 + tokp;
            vd[0]   = f2tf32(vv.x); vd[80]  = f2tf32(vv.y);
            vd[160] = f2tf32(vv.z); vd[240] = f2tf32(vv.w);
        }
        __syncthreads();

        // --- scores: S = Q * K^T (16 x 64 per warp) ---
        float s[8][4];
        #pragma unroll
        for (int nt = 0; nt < 8; nt++)
            #pragma unroll
            for (int e = 0; e < 4; e++) s[nt][e] = 0.f;

        #pragma unroll
        for (int k2 = 0; k2 < 4; k2++) {
            uint4 kb[8];
            #pragma unroll
            for (int nt = 0; nt < 8; nt++)
                kb[nt] = *(const uint4*)&Ks[(nt * 8 + g) * 80 + k2 * 16 + j * 4];
            #pragma unroll
            for (int nt = 0; nt < 8; nt++) {
                mma8(s[nt], qa[2*k2][0], qa[2*k2][1], qa[2*k2][2], qa[2*k2][3],
                     kb[nt].x, kb[nt].y);
                mma8(s[nt], qa[2*k2+1][0], qa[2*k2+1][1], qa[2*k2+1][2], qa[2*k2+1][3],
                     kb[nt].z, kb[nt].w);
            }
        }

        // --- online softmax (log2 domain) ---
        float r0 = -1e30f, r1 = -1e30f;
        #pragma unroll
        for (int nt = 0; nt < 8; nt++) {
            r0 = fmaxf(r0, fmaxf(s[nt][0], s[nt][1]));
            r1 = fmaxf(r1, fmaxf(s[nt][2], s[nt][3]));
        }
        r0 = fmaxf(r0, __shfl_xor_sync(0xffffffffu, r0, 1));
        r0 = fmaxf(r0, __shfl_xor_sync(0xffffffffu, r0, 2));
        r1 = fmaxf(r1, __shfl_xor_sync(0xffffffffu, r1, 1));
        r1 = fmaxf(r1, __shfl_xor_sync(0xffffffffu, r1, 2));
        float mn0 = fmaxf(m0, r0), mn1 = fmaxf(m1, r1);
        float sc0 = ex2f_fast(m0 - mn0), sc1 = ex2f_fast(m1 - mn1);
        float rs0 = 0.f, rs1 = 0.f;
        #pragma unroll
        for (int nt = 0; nt < 8; nt++) {
            int t0 = nt * 8 + 2 * j, t1 = t0 + 1;
            int t0p = (t0 & 48) + ((t0 & 15) & 3) * 4 + ((t0 & 15) >> 2);
            int t1p = (t1 & 48) + ((t1 & 15) & 3) * 4 + ((t1 & 15) >> 2);
            float p0 = ex2f_fast(s[nt][0] - mn0);
            float p1 = ex2f_fast(s[nt][1] - mn0);
            float p2 = ex2f_fast(s[nt][2] - mn1);
            float p3 = ex2f_fast(s[nt][3] - mn1);
            rs0 += p0 + p1; rs1 += p2 + p3;
            Ps[g * 80 + t0p]       = f2tf32(p0);
            Ps[g * 80 + t1p]       = f2tf32(p1);
            Ps[(g + 8) * 80 + t0p] = f2tf32(p2);
            Ps[(g + 8) * 80 + t1p] = f2tf32(p3);
            o[nt][0] *= sc0; o[nt][1] *= sc0;
            o[nt][2] *= sc1; o[nt][3] *= sc1;
        }
        rs0 += __shfl_xor_sync(0xffffffffu, rs0, 1);
        rs0 += __shfl_xor_sync(0xffffffffu, rs0, 2);
        rs1 += __shfl_xor_sync(0xffffffffu, rs1, 1);
        rs1 += __shfl_xor_sync(0xffffffffu, rs1, 2);
        l0 = l0 * sc0 + rs0; m0 = mn0;
        l1 = l1 * sc1 + rs1; m1 = mn1;
        __syncwarp();   // Ps is per-warp private; order STS before LDS

        // --- O += P * V ---
        #pragma unroll
        for (int k2 = 0; k2 < 4; k2++) {
            uint4 pa0 = *(const uint4*)&Ps[g * 80 + k2 * 16 + j * 4];
            uint4 pa1 = *(const uint4*)&Ps[(g + 8) * 80 + k2 * 16 + j * 4];
            #pragma unroll
            for (int nt = 0; nt < 8; nt++) {
                uint4 vb = *(const uint4*)&Vs[(nt * 8 + g) * 80 + k2 * 16 + j * 4];
                mma8(o[nt], pa0.x, pa1.x, pa0.y, pa1.y, vb.x, vb.y);
                mma8(o[nt], pa0.z, pa1.z, pa0.w, pa1.w, vb.z, vb.w);
            }
        }
        __syncthreads();   // protect K/V smem before next chunk overwrites
    }

    // --- normalize + store ---
    float inv0 = 1.f / l0, inv1 = 1.f / l1;
    size_t row = (size_t)(b * S + q0 + warp * 16 + g);
    #pragma unroll
    for (int nt = 0; nt < 8; nt++) {
        int col = h * HD + nt * 8 + 2 * j;
        *(float2*)&ctx[row * EMB + col]       = make_float2(o[nt][0] * inv0, o[nt][1] * inv0);
        *(float2*)&ctx[(row + 8) * EMB + col] = make_float2(o[nt][2] * inv1, o[nt][3] * inv1);
    }
}

// ---------------------------------------------------------------------------
extern "C" void kernel_launch(void* const* d_in, const int* in_sizes, int n_in,
                              void* d_out, int out_size)
{
    const float* query = (const float*)d_in[0];
    const float* key   = (const float*)d_in[1];
    const float* value = (const float*)d_in[2];
    const float* Wq    = (const float*)d_in[3];
    const float* Wk    = (const float*)d_in[4];
    const float* Wv    = (const float*)d_in[5];
    const float* Wo    = (const float*)d_in[6];
    float* out = (float*)d_out;

    float *gQ, *gK, *gV, *gC;
    cudaGetSymbolAddress((void**)&gQ, g_Q);
    cudaGetSymbolAddress((void**)&gK, g_K);
    cudaGetSymbolAddress((void**)&gV, g_V);
    cudaGetSymbolAddress((void**)&gC, g_C);

    cudaFuncSetAttribute(attn_tf32, cudaFuncAttributeMaxDynamicSharedMemorySize, ATTN_SMEM);

    // Projections (tensor cores, tf32)
    gemm_tf32<<<dim3(EMB / 128,    M_ROWS / 128), 256>>>(query, Wq, gQ, M_ROWS, EMB,    EMB);
    gemm_tf32<<<dim3(KV_DIM / 128, M_ROWS / 128), 256>>>(key,   Wk, gK, M_ROWS, KV_DIM, EMB);
    gemm_tf32<<<dim3(KV_DIM / 128, M_ROWS / 128), 256>>>(value, Wv, gV, M_ROWS, KV_DIM, EMB);

    // Attention (tensor cores, tf32, flash)
    attn_tf32<<<dim3(S / 64, NH, B), 128, ATTN_SMEM>>>(gQ, gK, gV, gC);

    // Output projection
    gemm_tf32<<<dim3(EMB / 128, M_ROWS / 128), 256>>>(gC, Wo, out, M_ROWS, EMB, EMB);
}